// round 15
// baseline (speedup 1.0000x reference)
#include <cuda_runtime.h>
#include <cuda_fp16.h>

#define NNODES 50000
#define NEDGES 800000
#define FDIM 64
#define NCLS 16
#define CAP 128   // per-node edge capacity (deg ~ Binomial(800k,1/50k); max ~45)

typedef unsigned long long ull;

// ---- device scratch (allocation-free; zero-initialized at load) ----
__device__ int    g_cnt[NNODES];                   // per-node fill counters (reset by agg2)
__device__ float  g_degw[NNODES];                  // weighted degree, from 0 (reset by agg2)
__device__ float  g_dinv[NNODES];
__device__ int2   g_edge[(size_t)NNODES * CAP];    // bucketed edges: {src, w bits}
__device__ __half g_bufAh[(size_t)NNODES * FDIM];  // GEMM outputs, fp16 (gather source)
__device__ float  g_bufB[(size_t)NNODES * FDIM];   // aggregated features, fp32

// ---------------- prologue ----------------
__global__ void k_edge(const int* __restrict__ ei,
                       const float* __restrict__ w, int e) {
    int i = blockIdx.x * blockDim.x + threadIdx.x;
    if (i < e) {
        int   r  = ei[i];
        int   c  = ei[e + i];
        float wv = w[i];
        atomicAdd(&g_degw[c], wv);
        int pos = atomicAdd(&g_cnt[c], 1);
        if (pos < CAP)
            g_edge[(size_t)c * CAP + pos] = make_int2(r, __float_as_int(wv));
    }
}

__global__ void k_dinv(int n) {
    int i = blockIdx.x * blockDim.x + threadIdx.x;
    if (i < n)
        g_dinv[i] = rsqrtf(1.0f + g_degw[i]);   // +1 = self-loop; always > 0
}

// ---------------- 64x64 GEMM: bufAh = fp16( act(X [+bias]) @ W ) ----------------
// 64 rows/block, 128 threads, 8 rows x 4 cols per thread, packed fma.rn.f32x2.
// Fill uses per-thread 4x4 register transpose -> STS.128 row-quads (no 16-way conflicts).
template <bool FROM_BUF>
__global__ void __launch_bounds__(128) k_gemm64(const float* __restrict__ Xext,
                         const float* __restrict__ bias,
                         const float* __restrict__ W, int n) {
    __shared__ __align__(16) float Ws[FDIM * FDIM];   // [k][c] row-major
    __shared__ __align__(16) float XsT[FDIM][68];     // [k][row], 64 rows + pad
    const int tid = threadIdx.x;                      // 0..127

    {
        const float4* W4 = (const float4*)W;
        float4* Ws4 = (float4*)Ws;
#pragma unroll
        for (int i = tid; i < FDIM * FDIM / 4; i += 128)
            Ws4[i] = W4[i];
    }

    const int row0 = blockIdx.x * 64;
    const float* X = FROM_BUF ? g_bufB : Xext;

    // ---- fill: coalesced loads, 4x4 register transpose, STS.128 stores ----
    {
        const int kq = tid & 15;          // k-quarter (4 floats)
        const int rg = tid >> 4;          // row-group of 8 (0..7)
        float4 b4 = make_float4(0.f, 0.f, 0.f, 0.f);
        if (FROM_BUF) b4 = *(const float4*)&bias[kq * 4];
#pragma unroll
        for (int h = 0; h < 2; h++) {
            const int rbase = rg * 8 + h * 4;
            float4 v[4];
#pragma unroll
            for (int j = 0; j < 4; j++) {
                int row = row0 + rbase + j;
                float4 t = make_float4(0.f, 0.f, 0.f, 0.f);
                if (row < n) t = *(const float4*)&X[(size_t)row * FDIM + kq * 4];
                if (FROM_BUF) {
                    t.x = fmaxf(t.x + b4.x, 0.f);
                    t.y = fmaxf(t.y + b4.y, 0.f);
                    t.z = fmaxf(t.z + b4.z, 0.f);
                    t.w = fmaxf(t.w + b4.w, 0.f);
                }
                v[j] = t;
            }
            *(float4*)&XsT[kq * 4 + 0][rbase] = make_float4(v[0].x, v[1].x, v[2].x, v[3].x);
            *(float4*)&XsT[kq * 4 + 1][rbase] = make_float4(v[0].y, v[1].y, v[2].y, v[3].y);
            *(float4*)&XsT[kq * 4 + 2][rbase] = make_float4(v[0].z, v[1].z, v[2].z, v[3].z);
            *(float4*)&XsT[kq * 4 + 3][rbase] = make_float4(v[0].w, v[1].w, v[2].w, v[3].w);
        }
    }
    __syncthreads();

    // ---- compute: 8 rows x 4 cols per thread ----
    const int c0 = (tid & 15) * 4;
    const int r0 = (tid >> 4) * 8;

    ull a0[4] = {0ull, 0ull, 0ull, 0ull};
    ull a1[4] = {0ull, 0ull, 0ull, 0ull};
    ull a2[4] = {0ull, 0ull, 0ull, 0ull};
    ull a3[4] = {0ull, 0ull, 0ull, 0ull};

#pragma unroll
    for (int k = 0; k < FDIM; k++) {
        ulonglong2 avl = *(const ulonglong2*)&XsT[k][r0];
        ulonglong2 avh = *(const ulonglong2*)&XsT[k][r0 + 4];
        float4 bv = *(const float4*)&Ws[k * FDIM + c0];
        ull bd0, bd1, bd2, bd3;
        asm("mov.b64 %0, {%1, %1};" : "=l"(bd0) : "f"(bv.x));
        asm("mov.b64 %0, {%1, %1};" : "=l"(bd1) : "f"(bv.y));
        asm("mov.b64 %0, {%1, %1};" : "=l"(bd2) : "f"(bv.z));
        asm("mov.b64 %0, {%1, %1};" : "=l"(bd3) : "f"(bv.w));
        asm("fma.rn.f32x2 %0, %1, %2, %0;" : "+l"(a0[0]) : "l"(avl.x), "l"(bd0));
        asm("fma.rn.f32x2 %0, %1, %2, %0;" : "+l"(a0[1]) : "l"(avl.x), "l"(bd1));
        asm("fma.rn.f32x2 %0, %1, %2, %0;" : "+l"(a0[2]) : "l"(avl.x), "l"(bd2));
        asm("fma.rn.f32x2 %0, %1, %2, %0;" : "+l"(a0[3]) : "l"(avl.x), "l"(bd3));
        asm("fma.rn.f32x2 %0, %1, %2, %0;" : "+l"(a1[0]) : "l"(avl.y), "l"(bd0));
        asm("fma.rn.f32x2 %0, %1, %2, %0;" : "+l"(a1[1]) : "l"(avl.y), "l"(bd1));
        asm("fma.rn.f32x2 %0, %1, %2, %0;" : "+l"(a1[2]) : "l"(avl.y), "l"(bd2));
        asm("fma.rn.f32x2 %0, %1, %2, %0;" : "+l"(a1[3]) : "l"(avl.y), "l"(bd3));
        asm("fma.rn.f32x2 %0, %1, %2, %0;" : "+l"(a2[0]) : "l"(avh.x), "l"(bd0));
        asm("fma.rn.f32x2 %0, %1, %2, %0;" : "+l"(a2[1]) : "l"(avh.x), "l"(bd1));
        asm("fma.rn.f32x2 %0, %1, %2, %0;" : "+l"(a2[2]) : "l"(avh.x), "l"(bd2));
        asm("fma.rn.f32x2 %0, %1, %2, %0;" : "+l"(a2[3]) : "l"(avh.x), "l"(bd3));
        asm("fma.rn.f32x2 %0, %1, %2, %0;" : "+l"(a3[0]) : "l"(avh.y), "l"(bd0));
        asm("fma.rn.f32x2 %0, %1, %2, %0;" : "+l"(a3[1]) : "l"(avh.y), "l"(bd1));
        asm("fma.rn.f32x2 %0, %1, %2, %0;" : "+l"(a3[2]) : "l"(avh.y), "l"(bd2));
        asm("fma.rn.f32x2 %0, %1, %2, %0;" : "+l"(a3[3]) : "l"(avh.y), "l"(bd3));
    }

    const int rowb = row0 + r0;
#pragma unroll
    for (int p = 0; p < 4; p++) {
        ull* ap = (p == 0) ? a0 : (p == 1) ? a1 : (p == 2) ? a2 : a3;
        float lo[4], hi[4];
#pragma unroll
        for (int c = 0; c < 4; c++)
            asm("mov.b64 {%0, %1}, %2;" : "=f"(lo[c]), "=f"(hi[c]) : "l"(ap[c]));
        int r = rowb + 2 * p;
        if (r < n) {
            __half2 h[2];
            h[0] = __float22half2_rn(make_float2(lo[0], lo[1]));
            h[1] = __float22half2_rn(make_float2(lo[2], lo[3]));
            *(uint2*)&g_bufAh[(size_t)r * FDIM + c0] = *(uint2*)h;
        }
        if (r + 1 < n) {
            __half2 h[2];
            h[0] = __float22half2_rn(make_float2(hi[0], hi[1]));
            h[1] = __float22half2_rn(make_float2(hi[2], hi[3]));
            *(uint2*)&g_bufAh[(size_t)(r + 1) * FDIM + c0] = *(uint2*)h;
        }
    }
}

// fp16x4 gather helper: acc (2x f32x2) += {nv,nv} * bufAh[src][4q..4q+3]
__device__ __forceinline__ void acc_half4(ull& accA, ull& accB, ull nvd, uint2 u) {
    float2 f0 = __half22float2(*(__half2*)&u.x);
    float2 f1 = __half22float2(*(__half2*)&u.y);
    ull p0, p1;
    asm("mov.b64 %0, {%1, %2};" : "=l"(p0) : "f"(f0.x), "f"(f0.y));
    asm("mov.b64 %0, {%1, %2};" : "=l"(p1) : "f"(f1.x), "f"(f1.y));
    asm("fma.rn.f32x2 %0, %1, %2, %0;" : "+l"(accA) : "l"(p0), "l"(nvd));
    asm("fma.rn.f32x2 %0, %1, %2, %0;" : "+l"(accB) : "l"(p1), "l"(nvd));
}

// ---------------- pull aggregation: bufB[v] = dv*( sum dinv[src]*w*bufAh[src] + dv*bufAh[v] ) ----------------
// 16 lanes per node, one uint2 (4 halves) per lane; packed f32x2 accumulation; unroll 4.
// RESET: last user of g_cnt/g_degw this call -> restore to zero for the next call/replay.
template <bool RESET>
__global__ void k_agg_pull(int n) {
    int gid = blockIdx.x * blockDim.x + threadIdx.x;
    int node = gid >> 4;
    int q    = gid & 15;
    if (node >= n) return;

    int cnt = g_cnt[node];
    if (cnt > CAP) cnt = CAP;
    float dv = g_dinv[node];
    const size_t base = (size_t)node * CAP;

    ull accA = 0ull, accB = 0ull;
    {
        ull dvd;
        asm("mov.b64 %0, {%1, %1};" : "=l"(dvd) : "f"(dv));
        uint2 us = __ldg(reinterpret_cast<const uint2*>(g_bufAh + (size_t)node * FDIM) + q);
        acc_half4(accA, accB, dvd, us);
    }

    int i = 0;
    for (; i + 4 <= cnt; i += 4) {
        int2 e0 = __ldg(g_edge + base + i + 0);
        int2 e1 = __ldg(g_edge + base + i + 1);
        int2 e2 = __ldg(g_edge + base + i + 2);
        int2 e3 = __ldg(g_edge + base + i + 3);
        float n0 = __ldg(g_dinv + e0.x) * __int_as_float(e0.y);
        float n1 = __ldg(g_dinv + e1.x) * __int_as_float(e1.y);
        float n2 = __ldg(g_dinv + e2.x) * __int_as_float(e2.y);
        float n3 = __ldg(g_dinv + e3.x) * __int_as_float(e3.y);
        uint2 u0 = __ldg(reinterpret_cast<const uint2*>(g_bufAh + (size_t)e0.x * FDIM) + q);
        uint2 u1 = __ldg(reinterpret_cast<const uint2*>(g_bufAh + (size_t)e1.x * FDIM) + q);
        uint2 u2 = __ldg(reinterpret_cast<const uint2*>(g_bufAh + (size_t)e2.x * FDIM) + q);
        uint2 u3 = __ldg(reinterpret_cast<const uint2*>(g_bufAh + (size_t)e3.x * FDIM) + q);
        ull d0, d1, d2, d3;
        asm("mov.b64 %0, {%1, %1};" : "=l"(d0) : "f"(n0));
        asm("mov.b64 %0, {%1, %1};" : "=l"(d1) : "f"(n1));
        asm("mov.b64 %0, {%1, %1};" : "=l"(d2) : "f"(n2));
        asm("mov.b64 %0, {%1, %1};" : "=l"(d3) : "f"(n3));
        acc_half4(accA, accB, d0, u0);
        acc_half4(accA, accB, d1, u1);
        acc_half4(accA, accB, d2, u2);
        acc_half4(accA, accB, d3, u3);
    }
    for (; i < cnt; i++) {
        int2 e0 = __ldg(g_edge + base + i);
        float n0 = __ldg(g_dinv + e0.x) * __int_as_float(e0.y);
        uint2 u0 = __ldg(reinterpret_cast<const uint2*>(g_bufAh + (size_t)e0.x * FDIM) + q);
        ull d0;
        asm("mov.b64 %0, {%1, %1};" : "=l"(d0) : "f"(n0));
        acc_half4(accA, accB, d0, u0);
    }

    float o0, o1, o2, o3;
    asm("mov.b64 {%0, %1}, %2;" : "=f"(o0), "=f"(o1) : "l"(accA));
    asm("mov.b64 {%0, %1}, %2;" : "=f"(o2), "=f"(o3) : "l"(accB));
    float4 o = make_float4(o0 * dv, o1 * dv, o2 * dv, o3 * dv);
    reinterpret_cast<float4*>(g_bufB + (size_t)node * FDIM)[q] = o;

    if (RESET && q == 0) {
        g_cnt[node]  = 0;
        g_degw[node] = 0.0f;
    }
}

// ---------------- head: relu(bufB + b2) @ Wout + bout -> softmax ----------------
__global__ void k_head(const float* __restrict__ b2,
                       const float* __restrict__ Wout,
                       const float* __restrict__ bout,
                       float* __restrict__ out, int n) {
    __shared__ float Ws[FDIM * NCLS];
    __shared__ float Hs[8][FDIM + 1];
    const int tid = threadIdx.x;   // 0..127

    for (int i = tid; i < FDIM * NCLS; i += 128) Ws[i] = Wout[i];

    int row0 = blockIdx.x * 8;
    for (int i = tid; i < 8 * FDIM; i += 128) {
        int rr = i >> 6, k = i & 63;
        int row = row0 + rr;
        float v = (row < n) ? g_bufB[(size_t)row * FDIM + k] : 0.0f;
        Hs[rr][k] = fmaxf(v + b2[k], 0.0f);
    }
    __syncthreads();

    int rr = tid >> 4;
    int c  = tid & 15;
    int row = row0 + rr;
    if (row < n) {
        float acc = bout[c];
#pragma unroll
        for (int k = 0; k < FDIM; k++)
            acc += Hs[rr][k] * Ws[k * NCLS + c];
        float m = acc;
#pragma unroll
        for (int off = 8; off; off >>= 1)
            m = fmaxf(m, __shfl_xor_sync(0xffffffffu, m, off, 16));
        float ex = __expf(acc - m);
        float s = ex;
#pragma unroll
        for (int off = 8; off; off >>= 1)
            s += __shfl_xor_sync(0xffffffffu, s, off, 16);
        out[(size_t)row * NCLS + c] = ex / s;
    }
}

// ---------------- launch ----------------
extern "C" void kernel_launch(void* const* d_in, const int* in_sizes, int n_in,
                              void* d_out, int out_size) {
    const float* x    = (const float*)d_in[0];
    const int*   ei   = (const int*)d_in[1];    // int32 (JAX x64 disabled)
    const float* w    = (const float*)d_in[2];
    const float* W1   = (const float*)d_in[3];
    const float* b1   = (const float*)d_in[4];
    const float* W2   = (const float*)d_in[5];
    const float* b2   = (const float*)d_in[6];
    const float* Wout = (const float*)d_in[7];
    const float* bout = (const float*)d_in[8];
    float*       out  = (float*)d_out;

    const int n = in_sizes[0] / FDIM;   // 50000
    const int e = in_sizes[2];          // 800000

    const int TB = 256;
    int gemmGrid = (n + 63) / 64;
    int aggGrid  = (int)(((size_t)n * 16 + TB - 1) / TB);

    // prologue: bucket edges + weighted degree (counters start at 0: zero-init
    // on first call, reset by agg2 on every call/replay), then dinv
    k_edge<<<(e + TB - 1) / TB, TB>>>(ei, w, e);
    k_dinv<<<(n + TB - 1) / TB, TB>>>(n);

    // layer 1
    k_gemm64<false><<<gemmGrid, 128>>>(x, b1, W1, n);
    k_agg_pull<false><<<aggGrid, TB>>>(n);

    // layer 2 (bias b1 + relu fused into GEMM load)
    k_gemm64<true><<<gemmGrid, 128>>>(x, b1, W2, n);
    k_agg_pull<true><<<aggGrid, TB>>>(n);   // resets g_cnt/g_degw for next call

    // head: bias b2 + relu + GEMM->16 + softmax
    k_head<<<(n + 7) / 8, 128>>>(b2, Wout, bout, out, n);
}

// round 16
// speedup vs baseline: 1.0798x; 1.0798x over previous
#include <cuda_runtime.h>
#include <cuda_fp16.h>

#define NNODES 50000
#define NEDGES 800000
#define FDIM 64
#define NCLS 16
#define CAP 128   // per-node edge capacity (deg ~ Binomial(800k,1/50k); max ~45)

typedef unsigned long long ull;

// ---- device scratch (allocation-free; zero-initialized at load) ----
__device__ int    g_cnt[NNODES];                   // per-node fill counters (reset by agg2)
__device__ float  g_degw[NNODES];                  // weighted degree, from 0 (reset by agg2)
__device__ float  g_dinv[NNODES];
__device__ int2   g_edge[(size_t)NNODES * CAP];    // bucketed edges: {src, w bits}
__device__ __half g_bufAh[(size_t)NNODES * FDIM];  // GEMM outputs, fp16 (gather source)
__device__ float  g_bufB[(size_t)NNODES * FDIM];   // aggregated features, fp32

// ---------------- prologue ----------------
__global__ void k_edge(const int* __restrict__ ei,
                       const float* __restrict__ w, int e) {
    int i = blockIdx.x * blockDim.x + threadIdx.x;
    if (i < e) {
        int   r  = ei[i];
        int   c  = ei[e + i];
        float wv = w[i];
        atomicAdd(&g_degw[c], wv);
        int pos = atomicAdd(&g_cnt[c], 1);
        if (pos < CAP)
            g_edge[(size_t)c * CAP + pos] = make_int2(r, __float_as_int(wv));
    }
}

__global__ void k_dinv(int n) {
    int i = blockIdx.x * blockDim.x + threadIdx.x;
    if (i < n)
        g_dinv[i] = rsqrtf(1.0f + g_degw[i]);   // +1 = self-loop; always > 0
}

// ---------------- 64x64 GEMM: bufAh = fp16( act(X [+bias]) @ W ) ----------------
// 64 rows/block, 128 threads, 8 rows x 4 cols per thread, packed fma.rn.f32x2.
// Fill uses per-thread 4x4 register transpose -> STS.128 row-quads (no 16-way conflicts).
template <bool FROM_BUF>
__global__ void __launch_bounds__(128) k_gemm64(const float* __restrict__ Xext,
                         const float* __restrict__ bias,
                         const float* __restrict__ W, int n) {
    __shared__ __align__(16) float Ws[FDIM * FDIM];   // [k][c] row-major
    __shared__ __align__(16) float XsT[FDIM][68];     // [k][row], 64 rows + pad
    const int tid = threadIdx.x;                      // 0..127

    {
        const float4* W4 = (const float4*)W;
        float4* Ws4 = (float4*)Ws;
#pragma unroll
        for (int i = tid; i < FDIM * FDIM / 4; i += 128)
            Ws4[i] = W4[i];
    }

    const int row0 = blockIdx.x * 64;
    const float* X = FROM_BUF ? g_bufB : Xext;

    // ---- fill: coalesced loads, 4x4 register transpose, STS.128 stores ----
    {
        const int kq = tid & 15;          // k-quarter (4 floats)
        const int rg = tid >> 4;          // row-group of 8 (0..7)
        float4 b4 = make_float4(0.f, 0.f, 0.f, 0.f);
        if (FROM_BUF) b4 = *(const float4*)&bias[kq * 4];
#pragma unroll
        for (int h = 0; h < 2; h++) {
            const int rbase = rg * 8 + h * 4;
            float4 v[4];
#pragma unroll
            for (int j = 0; j < 4; j++) {
                int row = row0 + rbase + j;
                float4 t = make_float4(0.f, 0.f, 0.f, 0.f);
                if (row < n) t = *(const float4*)&X[(size_t)row * FDIM + kq * 4];
                if (FROM_BUF) {
                    t.x = fmaxf(t.x + b4.x, 0.f);
                    t.y = fmaxf(t.y + b4.y, 0.f);
                    t.z = fmaxf(t.z + b4.z, 0.f);
                    t.w = fmaxf(t.w + b4.w, 0.f);
                }
                v[j] = t;
            }
            *(float4*)&XsT[kq * 4 + 0][rbase] = make_float4(v[0].x, v[1].x, v[2].x, v[3].x);
            *(float4*)&XsT[kq * 4 + 1][rbase] = make_float4(v[0].y, v[1].y, v[2].y, v[3].y);
            *(float4*)&XsT[kq * 4 + 2][rbase] = make_float4(v[0].z, v[1].z, v[2].z, v[3].z);
            *(float4*)&XsT[kq * 4 + 3][rbase] = make_float4(v[0].w, v[1].w, v[2].w, v[3].w);
        }
    }
    __syncthreads();

    // ---- compute: 8 rows x 4 cols per thread ----
    const int c0 = (tid & 15) * 4;
    const int r0 = (tid >> 4) * 8;

    ull a0[4] = {0ull, 0ull, 0ull, 0ull};
    ull a1[4] = {0ull, 0ull, 0ull, 0ull};
    ull a2[4] = {0ull, 0ull, 0ull, 0ull};
    ull a3[4] = {0ull, 0ull, 0ull, 0ull};

#pragma unroll
    for (int k = 0; k < FDIM; k++) {
        ulonglong2 avl = *(const ulonglong2*)&XsT[k][r0];
        ulonglong2 avh = *(const ulonglong2*)&XsT[k][r0 + 4];
        float4 bv = *(const float4*)&Ws[k * FDIM + c0];
        ull bd0, bd1, bd2, bd3;
        asm("mov.b64 %0, {%1, %1};" : "=l"(bd0) : "f"(bv.x));
        asm("mov.b64 %0, {%1, %1};" : "=l"(bd1) : "f"(bv.y));
        asm("mov.b64 %0, {%1, %1};" : "=l"(bd2) : "f"(bv.z));
        asm("mov.b64 %0, {%1, %1};" : "=l"(bd3) : "f"(bv.w));
        asm("fma.rn.f32x2 %0, %1, %2, %0;" : "+l"(a0[0]) : "l"(avl.x), "l"(bd0));
        asm("fma.rn.f32x2 %0, %1, %2, %0;" : "+l"(a0[1]) : "l"(avl.x), "l"(bd1));
        asm("fma.rn.f32x2 %0, %1, %2, %0;" : "+l"(a0[2]) : "l"(avl.x), "l"(bd2));
        asm("fma.rn.f32x2 %0, %1, %2, %0;" : "+l"(a0[3]) : "l"(avl.x), "l"(bd3));
        asm("fma.rn.f32x2 %0, %1, %2, %0;" : "+l"(a1[0]) : "l"(avl.y), "l"(bd0));
        asm("fma.rn.f32x2 %0, %1, %2, %0;" : "+l"(a1[1]) : "l"(avl.y), "l"(bd1));
        asm("fma.rn.f32x2 %0, %1, %2, %0;" : "+l"(a1[2]) : "l"(avl.y), "l"(bd2));
        asm("fma.rn.f32x2 %0, %1, %2, %0;" : "+l"(a1[3]) : "l"(avl.y), "l"(bd3));
        asm("fma.rn.f32x2 %0, %1, %2, %0;" : "+l"(a2[0]) : "l"(avh.x), "l"(bd0));
        asm("fma.rn.f32x2 %0, %1, %2, %0;" : "+l"(a2[1]) : "l"(avh.x), "l"(bd1));
        asm("fma.rn.f32x2 %0, %1, %2, %0;" : "+l"(a2[2]) : "l"(avh.x), "l"(bd2));
        asm("fma.rn.f32x2 %0, %1, %2, %0;" : "+l"(a2[3]) : "l"(avh.x), "l"(bd3));
        asm("fma.rn.f32x2 %0, %1, %2, %0;" : "+l"(a3[0]) : "l"(avh.y), "l"(bd0));
        asm("fma.rn.f32x2 %0, %1, %2, %0;" : "+l"(a3[1]) : "l"(avh.y), "l"(bd1));
        asm("fma.rn.f32x2 %0, %1, %2, %0;" : "+l"(a3[2]) : "l"(avh.y), "l"(bd2));
        asm("fma.rn.f32x2 %0, %1, %2, %0;" : "+l"(a3[3]) : "l"(avh.y), "l"(bd3));
    }

    const int rowb = row0 + r0;
#pragma unroll
    for (int p = 0; p < 4; p++) {
        ull* ap = (p == 0) ? a0 : (p == 1) ? a1 : (p == 2) ? a2 : a3;
        float lo[4], hi[4];
#pragma unroll
        for (int c = 0; c < 4; c++)
            asm("mov.b64 {%0, %1}, %2;" : "=f"(lo[c]), "=f"(hi[c]) : "l"(ap[c]));
        int r = rowb + 2 * p;
        if (r < n) {
            __half2 h[2];
            h[0] = __float22half2_rn(make_float2(lo[0], lo[1]));
            h[1] = __float22half2_rn(make_float2(lo[2], lo[3]));
            *(uint2*)&g_bufAh[(size_t)r * FDIM + c0] = *(uint2*)h;
        }
        if (r + 1 < n) {
            __half2 h[2];
            h[0] = __float22half2_rn(make_float2(hi[0], hi[1]));
            h[1] = __float22half2_rn(make_float2(hi[2], hi[3]));
            *(uint2*)&g_bufAh[(size_t)(r + 1) * FDIM + c0] = *(uint2*)h;
        }
    }
}

// fp16x8 gather helper: accumulate nv * bufAh[src][8q .. 8q+7] into acc[8] (fp32)
__device__ __forceinline__ void acc_half8(float* acc, float nv, uint4 u) {
    float2 f0 = __half22float2(*(__half2*)&u.x);
    float2 f1 = __half22float2(*(((__half2*)&u.x) + 1));
    float2 f2 = __half22float2(*(__half2*)&u.z);
    float2 f3 = __half22float2(*(((__half2*)&u.z) + 1));
    acc[0] += nv * f0.x;  acc[1] += nv * f0.y;
    acc[2] += nv * f1.x;  acc[3] += nv * f1.y;
    acc[4] += nv * f2.x;  acc[5] += nv * f2.y;
    acc[6] += nv * f3.x;  acc[7] += nv * f3.y;
}

// ---------------- pull aggregation: bufB[v] = dv*( sum dinv[src]*w*bufAh[src] + dv*bufAh[v] ) ----------------
// 8 lanes per node, one uint4 (8 halves) per lane; fp32 accumulation; unroll 8 for MLP.
// RESET: last user of g_cnt/g_degw this call -> restore to zero for the next call/replay.
template <bool RESET>
__global__ void k_agg_pull(int n) {
    int gid = blockIdx.x * blockDim.x + threadIdx.x;
    int node = gid >> 3;
    int q    = gid & 7;
    if (node >= n) return;

    int cnt = g_cnt[node];
    if (cnt > CAP) cnt = CAP;
    float dv = g_dinv[node];
    const size_t base = (size_t)node * CAP;
    const uint4* selfp = reinterpret_cast<const uint4*>(g_bufAh + (size_t)node * FDIM) + q;

    float acc[8] = {0.f, 0.f, 0.f, 0.f, 0.f, 0.f, 0.f, 0.f};
    acc_half8(acc, dv, __ldg(selfp));

    int i = 0;
    for (; i + 8 <= cnt; i += 8) {
        int2 er[8];
#pragma unroll
        for (int j = 0; j < 8; j++) er[j] = __ldg(g_edge + base + i + j);
        float nv[8];
#pragma unroll
        for (int j = 0; j < 8; j++) nv[j] = __ldg(g_dinv + er[j].x) * __int_as_float(er[j].y);
        uint4 u[8];
#pragma unroll
        for (int j = 0; j < 8; j++)
            u[j] = __ldg(reinterpret_cast<const uint4*>(g_bufAh + (size_t)er[j].x * FDIM) + q);
#pragma unroll
        for (int j = 0; j < 8; j++)
            acc_half8(acc, nv[j], u[j]);
    }
    for (; i + 4 <= cnt; i += 4) {
        int2 er[4];
#pragma unroll
        for (int j = 0; j < 4; j++) er[j] = __ldg(g_edge + base + i + j);
        float nv[4];
#pragma unroll
        for (int j = 0; j < 4; j++) nv[j] = __ldg(g_dinv + er[j].x) * __int_as_float(er[j].y);
        uint4 u[4];
#pragma unroll
        for (int j = 0; j < 4; j++)
            u[j] = __ldg(reinterpret_cast<const uint4*>(g_bufAh + (size_t)er[j].x * FDIM) + q);
#pragma unroll
        for (int j = 0; j < 4; j++)
            acc_half8(acc, nv[j], u[j]);
    }
    for (; i < cnt; i++) {
        int2 e0 = __ldg(g_edge + base + i);
        float n0 = __ldg(g_dinv + e0.x) * __int_as_float(e0.y);
        uint4 u0 = __ldg(reinterpret_cast<const uint4*>(g_bufAh + (size_t)e0.x * FDIM) + q);
        acc_half8(acc, n0, u0);
    }

    float4 o0 = make_float4(acc[0] * dv, acc[1] * dv, acc[2] * dv, acc[3] * dv);
    float4 o1 = make_float4(acc[4] * dv, acc[5] * dv, acc[6] * dv, acc[7] * dv);
    float4* dst = reinterpret_cast<float4*>(g_bufB + (size_t)node * FDIM) + q * 2;
    dst[0] = o0;
    dst[1] = o1;

    if (RESET && q == 0) {
        g_cnt[node]  = 0;
        g_degw[node] = 0.0f;
    }
}

// ---------------- head: relu(bufB + b2) @ Wout + bout -> softmax ----------------
__global__ void k_head(const float* __restrict__ b2,
                       const float* __restrict__ Wout,
                       const float* __restrict__ bout,
                       float* __restrict__ out, int n) {
    __shared__ float Ws[FDIM * NCLS];
    __shared__ float Hs[8][FDIM + 1];
    const int tid = threadIdx.x;   // 0..127

    for (int i = tid; i < FDIM * NCLS; i += 128) Ws[i] = Wout[i];

    int row0 = blockIdx.x * 8;
    for (int i = tid; i < 8 * FDIM; i += 128) {
        int rr = i >> 6, k = i & 63;
        int row = row0 + rr;
        float v = (row < n) ? g_bufB[(size_t)row * FDIM + k] : 0.0f;
        Hs[rr][k] = fmaxf(v + b2[k], 0.0f);
    }
    __syncthreads();

    int rr = tid >> 4;
    int c  = tid & 15;
    int row = row0 + rr;
    if (row < n) {
        float acc = bout[c];
#pragma unroll
        for (int k = 0; k < FDIM; k++)
            acc += Hs[rr][k] * Ws[k * NCLS + c];
        float m = acc;
#pragma unroll
        for (int off = 8; off; off >>= 1)
            m = fmaxf(m, __shfl_xor_sync(0xffffffffu, m, off, 16));
        float ex = __expf(acc - m);
        float s = ex;
#pragma unroll
        for (int off = 8; off; off >>= 1)
            s += __shfl_xor_sync(0xffffffffu, s, off, 16);
        out[(size_t)row * NCLS + c] = ex / s;
    }
}

// ---------------- launch ----------------
extern "C" void kernel_launch(void* const* d_in, const int* in_sizes, int n_in,
                              void* d_out, int out_size) {
    const float* x    = (const float*)d_in[0];
    const int*   ei   = (const int*)d_in[1];    // int32 (JAX x64 disabled)
    const float* w    = (const float*)d_in[2];
    const float* W1   = (const float*)d_in[3];
    const float* b1   = (const float*)d_in[4];
    const float* W2   = (const float*)d_in[5];
    const float* b2   = (const float*)d_in[6];
    const float* Wout = (const float*)d_in[7];
    const float* bout = (const float*)d_in[8];
    float*       out  = (float*)d_out;

    const int n = in_sizes[0] / FDIM;   // 50000
    const int e = in_sizes[2];          // 800000

    const int TB = 256;
    int gemmGrid = (n + 63) / 64;
    int aggGrid  = (int)(((size_t)n * 8 + TB - 1) / TB);

    // prologue: bucket edges + weighted degree (counters start at 0: zero-init
    // on first call, reset by agg2 on every call/replay), then dinv
    k_edge<<<(e + TB - 1) / TB, TB>>>(ei, w, e);
    k_dinv<<<(n + TB - 1) / TB, TB>>>(n);

    // layer 1
    k_gemm64<false><<<gemmGrid, 128>>>(x, b1, W1, n);
    k_agg_pull<false><<<aggGrid, TB>>>(n);

    // layer 2 (bias b1 + relu fused into GEMM load)
    k_gemm64<true><<<gemmGrid, 128>>>(x, b1, W2, n);
    k_agg_pull<true><<<aggGrid, TB>>>(n);   // resets g_cnt/g_degw for next call

    // head: bias b2 + relu + GEMM->16 + softmax
    k_head<<<(n + 7) / 8, 128>>>(b2, Wout, bout, out, n);
}

// round 17
// speedup vs baseline: 1.1592x; 1.0735x over previous
#include <cuda_runtime.h>
#include <cuda_fp16.h>

#define NNODES 50000
#define NEDGES 800000
#define FDIM 64
#define NCLS 16
#define CAP 128   // per-node edge capacity (deg ~ Binomial(800k,1/50k); max ~45)

typedef unsigned long long ull;

// ---- device scratch (allocation-free; zero-initialized at load) ----
__device__ int    g_cnt[NNODES];                   // per-node fill counters (reset by agg2)
__device__ float  g_degw[NNODES];                  // weighted degree, from 0 (reset by agg2)
__device__ float  g_dinv[NNODES];
__device__ int2   g_edge[(size_t)NNODES * CAP];    // bucketed edges: {src, w bits}
__device__ __half g_bufAh[(size_t)NNODES * FDIM];  // GEMM outputs, fp16 (gather source)
__device__ float  g_bufB[(size_t)NNODES * FDIM];   // aggregated features, fp32

// ---------------- prologue ----------------
__global__ void k_edge(const int* __restrict__ ei,
                       const float* __restrict__ w, int e) {
    int i = blockIdx.x * blockDim.x + threadIdx.x;
    if (i < e) {
        int   r  = ei[i];
        int   c  = ei[e + i];
        float wv = w[i];
        atomicAdd(&g_degw[c], wv);
        int pos = atomicAdd(&g_cnt[c], 1);
        if (pos < CAP)
            g_edge[(size_t)c * CAP + pos] = make_int2(r, __float_as_int(wv));
    }
}

__global__ void k_dinv(int n) {
    int i = blockIdx.x * blockDim.x + threadIdx.x;
    if (i < n)
        g_dinv[i] = rsqrtf(1.0f + g_degw[i]);   // +1 = self-loop; always > 0
}

// ---------------- 64x64 GEMM via HMMA: bufAh = fp16( act(X [+bias]) @ W ) ----------------
// 64 rows/block, 128 threads (4 warps). A tile fp16 in smem (bias+relu fused at
// load), W fp16 [k][n] in smem. Each warp: 16 rows x 64 cols via
// mma.sync.m16n8k16 (4 k-steps x 8 n-tiles), fp32 accum, fp16 store.
template <bool FROM_BUF>
__global__ void __launch_bounds__(128) k_gemm_mma(const float* __restrict__ Xext,
                                                  const float* __restrict__ bias,
                                                  const float* __restrict__ W, int n) {
    __shared__ __align__(16) __half Ah[64][72];   // [row][k], 144B stride (16B mult.)
    __shared__ __align__(16) __half Wh[64][72];   // [k][n]
    const int tid  = threadIdx.x;
    const int lane = tid & 31;
    const int warp = tid >> 5;
    const int row0 = blockIdx.x * 64;
    const float* X = FROM_BUF ? g_bufB : Xext;

    // fill Wh[k][n] (fp32 -> fp16)
    for (int i = tid; i < 64 * 16; i += 128) {
        int k = i >> 4, nq = i & 15;
        float4 v = *(const float4*)&W[k * FDIM + nq * 4];
        __half2 h0 = __float22half2_rn(make_float2(v.x, v.y));
        __half2 h1 = __float22half2_rn(make_float2(v.z, v.w));
        uint2 u = make_uint2(*(unsigned*)&h0, *(unsigned*)&h1);
        *(uint2*)&Wh[k][nq * 4] = u;
    }

    // fill Ah[row][k] with fused bias+relu (FROM_BUF) and fp16 convert
    {
        const int kq = tid & 15;
        float4 b4 = make_float4(0.f, 0.f, 0.f, 0.f);
        if (FROM_BUF) b4 = *(const float4*)&bias[kq * 4];
        for (int i = tid; i < 64 * 16; i += 128) {
            int rr = i >> 4;
            int row = row0 + rr;
            float4 t = make_float4(0.f, 0.f, 0.f, 0.f);
            if (row < n) t = *(const float4*)&X[(size_t)row * FDIM + kq * 4];
            if (FROM_BUF) {
                t.x = fmaxf(t.x + b4.x, 0.f);
                t.y = fmaxf(t.y + b4.y, 0.f);
                t.z = fmaxf(t.z + b4.z, 0.f);
                t.w = fmaxf(t.w + b4.w, 0.f);
            }
            __half2 h0 = __float22half2_rn(make_float2(t.x, t.y));
            __half2 h1 = __float22half2_rn(make_float2(t.z, t.w));
            uint2 u = make_uint2(*(unsigned*)&h0, *(unsigned*)&h1);
            *(uint2*)&Ah[rr][kq * 4] = u;
        }
    }
    __syncthreads();

    // compute: warp owns rows [warp*16, warp*16+16), all 64 cols
    const int wr0 = warp * 16;
    float d[8][4];
#pragma unroll
    for (int t = 0; t < 8; t++)
#pragma unroll
        for (int c = 0; c < 4; c++) d[t][c] = 0.f;

#pragma unroll
    for (int k0 = 0; k0 < FDIM; k0 += 16) {
        unsigned a0, a1, a2, a3;
        {
            unsigned aaddr = (unsigned)__cvta_generic_to_shared(
                &Ah[wr0 + (lane & 15)][k0 + (lane >> 4) * 8]);
            asm volatile("ldmatrix.sync.aligned.m8n8.x4.shared.b16 {%0,%1,%2,%3}, [%4];"
                         : "=r"(a0), "=r"(a1), "=r"(a2), "=r"(a3) : "r"(aaddr));
        }
#pragma unroll
        for (int nt = 0; nt < 4; nt++) {   // covers n-tiles 2nt and 2nt+1
            unsigned b0, b1, b2, b3;
            unsigned baddr = (unsigned)__cvta_generic_to_shared(
                &Wh[k0 + (lane & 15)][nt * 16 + (lane >> 4) * 8]);
            asm volatile("ldmatrix.sync.aligned.m8n8.x4.trans.shared.b16 {%0,%1,%2,%3}, [%4];"
                         : "=r"(b0), "=r"(b1), "=r"(b2), "=r"(b3) : "r"(baddr));
            asm volatile("mma.sync.aligned.m16n8k16.row.col.f32.f16.f16.f32 "
                         "{%0,%1,%2,%3}, {%4,%5,%6,%7}, {%8,%9}, {%0,%1,%2,%3};"
                         : "+f"(d[2*nt][0]), "+f"(d[2*nt][1]), "+f"(d[2*nt][2]), "+f"(d[2*nt][3])
                         : "r"(a0), "r"(a1), "r"(a2), "r"(a3), "r"(b0), "r"(b1));
            asm volatile("mma.sync.aligned.m16n8k16.row.col.f32.f16.f16.f32 "
                         "{%0,%1,%2,%3}, {%4,%5,%6,%7}, {%8,%9}, {%0,%1,%2,%3};"
                         : "+f"(d[2*nt+1][0]), "+f"(d[2*nt+1][1]), "+f"(d[2*nt+1][2]), "+f"(d[2*nt+1][3])
                         : "r"(a0), "r"(a1), "r"(a2), "r"(a3), "r"(b2), "r"(b3));
        }
    }

    // epilogue: C fragment (m16n8 f32) -> fp16 global stores
    const int r    = lane >> 2;          // 0..7
    const int cofs = (lane & 3) * 2;     // 0,2,4,6
    const int grow = row0 + wr0 + r;
#pragma unroll
    for (int t = 0; t < 8; t++) {
        int c = t * 8 + cofs;
        if (grow < n) {
            __half2 h = __float22half2_rn(make_float2(d[t][0], d[t][1]));
            *(__half2*)&g_bufAh[(size_t)grow * FDIM + c] = h;
        }
        if (grow + 8 < n) {
            __half2 h = __float22half2_rn(make_float2(d[t][2], d[t][3]));
            *(__half2*)&g_bufAh[(size_t)(grow + 8) * FDIM + c] = h;
        }
    }
}

// fp16x8 gather helper: accumulate nv * bufAh[src][8q .. 8q+7] into acc[8] (fp32)
__device__ __forceinline__ void acc_half8(float* acc, float nv, uint4 u) {
    float2 f0 = __half22float2(*(__half2*)&u.x);
    float2 f1 = __half22float2(*(((__half2*)&u.x) + 1));
    float2 f2 = __half22float2(*(__half2*)&u.z);
    float2 f3 = __half22float2(*(((__half2*)&u.z) + 1));
    acc[0] += nv * f0.x;  acc[1] += nv * f0.y;
    acc[2] += nv * f1.x;  acc[3] += nv * f1.y;
    acc[4] += nv * f2.x;  acc[5] += nv * f2.y;
    acc[6] += nv * f3.x;  acc[7] += nv * f3.y;
}

// ---------------- pull aggregation: bufB[v] = dv*( sum dinv[src]*w*bufAh[src] + dv*bufAh[v] ) ----------------
// 8 lanes per node, one uint4 (8 halves) per lane; fp32 accumulation; unroll 8 for MLP.
template <bool RESET>
__global__ void k_agg_pull(int n) {
    int gid = blockIdx.x * blockDim.x + threadIdx.x;
    int node = gid >> 3;
    int q    = gid & 7;
    if (node >= n) return;

    int cnt = g_cnt[node];
    if (cnt > CAP) cnt = CAP;
    float dv = g_dinv[node];
    const size_t base = (size_t)node * CAP;
    const uint4* selfp = reinterpret_cast<const uint4*>(g_bufAh + (size_t)node * FDIM) + q;

    float acc[8] = {0.f, 0.f, 0.f, 0.f, 0.f, 0.f, 0.f, 0.f};
    acc_half8(acc, dv, __ldg(selfp));

    int i = 0;
    for (; i + 8 <= cnt; i += 8) {
        int2 er[8];
#pragma unroll
        for (int j = 0; j < 8; j++) er[j] = __ldg(g_edge + base + i + j);
        float nv[8];
#pragma unroll
        for (int j = 0; j < 8; j++) nv[j] = __ldg(g_dinv + er[j].x) * __int_as_float(er[j].y);
        uint4 u[8];
#pragma unroll
        for (int j = 0; j < 8; j++)
            u[j] = __ldg(reinterpret_cast<const uint4*>(g_bufAh + (size_t)er[j].x * FDIM) + q);
#pragma unroll
        for (int j = 0; j < 8; j++)
            acc_half8(acc, nv[j], u[j]);
    }
    for (; i + 4 <= cnt; i += 4) {
        int2 er[4];
#pragma unroll
        for (int j = 0; j < 4; j++) er[j] = __ldg(g_edge + base + i + j);
        float nv[4];
#pragma unroll
        for (int j = 0; j < 4; j++) nv[j] = __ldg(g_dinv + er[j].x) * __int_as_float(er[j].y);
        uint4 u[4];
#pragma unroll
        for (int j = 0; j < 4; j++)
            u[j] = __ldg(reinterpret_cast<const uint4*>(g_bufAh + (size_t)er[j].x * FDIM) + q);
#pragma unroll
        for (int j = 0; j < 4; j++)
            acc_half8(acc, nv[j], u[j]);
    }
    for (; i < cnt; i++) {
        int2 e0 = __ldg(g_edge + base + i);
        float n0 = __ldg(g_dinv + e0.x) * __int_as_float(e0.y);
        uint4 u0 = __ldg(reinterpret_cast<const uint4*>(g_bufAh + (size_t)e0.x * FDIM) + q);
        acc_half8(acc, n0, u0);
    }

    float4 o0 = make_float4(acc[0] * dv, acc[1] * dv, acc[2] * dv, acc[3] * dv);
    float4 o1 = make_float4(acc[4] * dv, acc[5] * dv, acc[6] * dv, acc[7] * dv);
    float4* dst = reinterpret_cast<float4*>(g_bufB + (size_t)node * FDIM) + q * 2;
    dst[0] = o0;
    dst[1] = o1;

    if (RESET && q == 0) {
        g_cnt[node]  = 0;
        g_degw[node] = 0.0f;
    }
}

// ---------------- head: relu(bufB + b2) @ Wout + bout -> softmax ----------------
__global__ void k_head(const float* __restrict__ b2,
                       const float* __restrict__ Wout,
                       const float* __restrict__ bout,
                       float* __restrict__ out, int n) {
    __shared__ float Ws[FDIM * NCLS];
    __shared__ float Hs[8][FDIM + 1];
    const int tid = threadIdx.x;   // 0..127

    for (int i = tid; i < FDIM * NCLS; i += 128) Ws[i] = Wout[i];

    int row0 = blockIdx.x * 8;
    for (int i = tid; i < 8 * FDIM; i += 128) {
        int rr = i >> 6, k = i & 63;
        int row = row0 + rr;
        float v = (row < n) ? g_bufB[(size_t)row * FDIM + k] : 0.0f;
        Hs[rr][k] = fmaxf(v + b2[k], 0.0f);
    }
    __syncthreads();

    int rr = tid >> 4;
    int c  = tid & 15;
    int row = row0 + rr;
    if (row < n) {
        float acc = bout[c];
#pragma unroll
        for (int k = 0; k < FDIM; k++)
            acc += Hs[rr][k] * Ws[k * NCLS + c];
        float m = acc;
#pragma unroll
        for (int off = 8; off; off >>= 1)
            m = fmaxf(m, __shfl_xor_sync(0xffffffffu, m, off, 16));
        float ex = __expf(acc - m);
        float s = ex;
#pragma unroll
        for (int off = 8; off; off >>= 1)
            s += __shfl_xor_sync(0xffffffffu, s, off, 16);
        out[(size_t)row * NCLS + c] = ex / s;
    }
}

// ---------------- launch ----------------
extern "C" void kernel_launch(void* const* d_in, const int* in_sizes, int n_in,
                              void* d_out, int out_size) {
    const float* x    = (const float*)d_in[0];
    const int*   ei   = (const int*)d_in[1];    // int32 (JAX x64 disabled)
    const float* w    = (const float*)d_in[2];
    const float* W1   = (const float*)d_in[3];
    const float* b1   = (const float*)d_in[4];
    const float* W2   = (const float*)d_in[5];
    const float* b2   = (const float*)d_in[6];
    const float* Wout = (const float*)d_in[7];
    const float* bout = (const float*)d_in[8];
    float*       out  = (float*)d_out;

    const int n = in_sizes[0] / FDIM;   // 50000
    const int e = in_sizes[2];          // 800000

    const int TB = 256;
    int gemmGrid = (n + 63) / 64;
    int aggGrid  = (int)(((size_t)n * 8 + TB - 1) / TB);

    // prologue: bucket edges + weighted degree (counters start at 0: zero-init
    // on first call, reset by agg2 on every call/replay), then dinv
    k_edge<<<(e + TB - 1) / TB, TB>>>(ei, w, e);
    k_dinv<<<(n + TB - 1) / TB, TB>>>(n);

    // layer 1
    k_gemm_mma<false><<<gemmGrid, 128>>>(x, b1, W1, n);
    k_agg_pull<false><<<aggGrid, TB>>>(n);

    // layer 2 (bias b1 + relu fused into GEMM load)
    k_gemm_mma<true><<<gemmGrid, 128>>>(x, b1, W2, n);
    k_agg_pull<true><<<aggGrid, TB>>>(n);   // resets g_cnt/g_degw for next call

    // head: bias b2 + relu + GEMM->16 + softmax
    k_head<<<(n + 7) / 8, 128>>>(b2, Wout, bout, out, n);
}